// round 15
// baseline (speedup 1.0000x reference)
#include <cuda_runtime.h>
#include <cstdint>

// z = sum_{p,q,r} C[p*9+q*3+r] * u0_p * u1_q * u2_r,  u_i = (1, cos x_i, sin x_i)
//
// SINGLE kernel:
//   - all threads front-batch 8 loads, then compute all 24 sincos (independent
//     of the coefficients; ~1-2us of work)
//   - meanwhile warp 0 of block 0 builds the 27 coefficients (~500 cyc) into
//     d_C and raises g_ready (threadfence-released)
//   - each block's thread 0 spin-waits on g_ready (already set by then),
//     block reads d_C -> shared, finishes the trilinear form
//   - done-counter: last block resets the flags (graph-replay safe)
// Deadlock-free: launch_bounds(256,4) => >=592 co-resident blocks >= grid 512.

__device__ float d_C[27];
__device__ volatile int g_ready;
__device__ int g_done;

static constexpr int SPT = 8;
static constexpr int BLOCK = 256;

__global__ void __launch_bounds__(BLOCK, 4)
vqc_one(const float4* __restrict__ in, float* __restrict__ out,
        const float* __restrict__ qw, int B) {
    const unsigned FULL = 0xFFFFFFFFu;
    const int t = threadIdx.x;
    const int T = gridDim.x * BLOCK;
    const int gidx = blockIdx.x * BLOCK + t;

    // ---- 1. Front-batch ALL loads ------------------------------------------
    float4 x[SPT];
    #pragma unroll
    for (int k = 0; k < SPT; k++) {
        int i = gidx + k * T;
        i = (i < B) ? i : (B - 1);
        x[k] = in[(size_t)i * 2];        // first 16B of the 32B row
    }

    // ---- 2. Block 0, warp 0: build coefficients ----------------------------
    if (blockIdx.x == 0 && t < 32) {
        const int lane = t;

        float ang = (lane < 18) ? 0.5f * qw[lane] : 0.f;
        float sh, ch;
        __sincosf(ang, &sh, &ch);

        const int j = lane & 7;
        float sr[8], si[8];
        #pragma unroll
        for (int m = 0; m < 8; m++) { sr[m] = 0.f; si[m] = 0.f; }
        sr[j] = 1.0f;

        #pragma unroll
        for (int g = 0; g < 9; g++) {        // layer = g/3, qubit = g%3
            const int bit = 4 >> (g % 3);
            float cy = __shfl_sync(FULL, ch, 2 * g);
            float sy = __shfl_sync(FULL, sh, 2 * g);
            float cz = __shfl_sync(FULL, ch, 2 * g + 1);
            float sz = __shfl_sync(FULL, sh, 2 * g + 1);

            #pragma unroll
            for (int m = 0; m < 8; m++) {    // RY
                if (m & bit) continue;
                int m1 = m | bit;
                float ar = sr[m],  ai = si[m];
                float br = sr[m1], bi = si[m1];
                sr[m]  = cy * ar - sy * br;  si[m]  = cy * ai - sy * bi;
                sr[m1] = sy * ar + cy * br;  si[m1] = sy * ai + cy * bi;
            }
            #pragma unroll
            for (int m = 0; m < 8; m++) {    // RZ
                float ar = sr[m], ai = si[m];
                if (m & bit) { sr[m] = cz * ar - sz * ai; si[m] = cz * ai + sz * ar; }
                else         { sr[m] = cz * ar + sz * ai; si[m] = cz * ai - sz * ar; }
            }
            if (g % 3 == 2) {
                #pragma unroll
                for (int m = 4; m < 6; m++) {    // CNOT01: swap (4,6),(5,7)
                    int m1 = m | 2; float tmp;
                    tmp = sr[m]; sr[m] = sr[m1]; sr[m1] = tmp;
                    tmp = si[m]; si[m] = si[m1]; si[m1] = tmp;
                }
                #pragma unroll
                for (int m = 2; m < 8; m += 4) { // CNOT12: swap (2,3),(6,7)
                    int m1 = m | 1; float tmp;
                    tmp = sr[m]; sr[m] = sr[m1]; sr[m1] = tmp;
                    tmp = si[m]; si[m] = si[m1]; si[m1] = tmp;
                }
            }
        }

        // A[jj][kk] via shfl gathers (columns live in lanes 0..7).
        // This lane owns entries e = lane and e+32 of the 8x8 A.
        const int jj1 = lane >> 3,       kk = lane & 7;
        const int jj2 = 4 + (lane >> 3);
        float a1 = 0.f, a2 = 0.f;
        #pragma unroll
        for (int m = 0; m < 8; m++) {
            float sgn = (m & 4) ? -1.f : 1.f;
            float urk  = __shfl_sync(FULL, sr[m], kk);
            float uik  = __shfl_sync(FULL, si[m], kk);
            float urj1 = __shfl_sync(FULL, sr[m], jj1);
            float uij1 = __shfl_sync(FULL, si[m], jj1);
            float urj2 = __shfl_sync(FULL, sr[m], jj2);
            float uij2 = __shfl_sync(FULL, si[m], jj2);
            a1 = fmaf(sgn, urj1 * urk + uij1 * uik, a1);
            a2 = fmaf(sgn, urj2 * urk + uij2 * uik, a2);
        }
        // Stash A in shared for the sparse contraction.
        __shared__ float Aj[8][8];
        Aj[jj1][kk] = a1;
        Aj[jj2][kk] = a2;
        __syncwarp();

        // Sparse direct contraction: C[p,q,r] touches exactly 8 A-entries.
        if (lane < 27) {
            const int p = lane / 9, q = (lane / 3) % 3, r = lane % 3;
            float csum = 0.f;
            #pragma unroll
            for (int i0 = 0; i0 < 2; i0++) {
                int b0 = (p == 2) ? 1 - i0 : i0;
                float w0 = (p == 1 && i0 == 1) ? -0.5f : 0.5f;
                #pragma unroll
                for (int i1 = 0; i1 < 2; i1++) {
                    int b1 = (q == 2) ? 1 - i1 : i1;
                    float w1 = (q == 1 && i1 == 1) ? -0.5f : 0.5f;
                    float w01 = w0 * w1;
                    #pragma unroll
                    for (int i2 = 0; i2 < 2; i2++) {
                        int b2 = (r == 2) ? 1 - i2 : i2;
                        float w2 = (r == 1 && i2 == 1) ? -0.5f : 0.5f;
                        csum = fmaf(w01 * w2,
                                    Aj[i0 * 4 + i1 * 2 + i2][b0 * 4 + b1 * 2 + b2],
                                    csum);
                    }
                }
            }
            d_C[lane] = csum;
        }
        __threadfence();                       // release d_C
        if (lane == 0) g_ready = 1;            // raise flag (volatile store)
    }

    // ---- 3. All trig (independent of coefficients) -------------------------
    float C0[SPT], S0[SPT], C1[SPT], S1[SPT], C2[SPT], S2[SPT];
    #pragma unroll
    for (int k = 0; k < SPT; k++) {
        __sincosf(x[k].x, &S0[k], &C0[k]);
        __sincosf(x[k].y, &S1[k], &C1[k]);
        __sincosf(x[k].z, &S2[k], &C2[k]);
    }

    // ---- 4. Acquire coefficients -------------------------------------------
    __shared__ float cs[27];
    if (t == 0) {
        while (g_ready == 0) { }               // short spin; flag set early
    }
    __syncthreads();
    if (t < 27) cs[t] = d_C[t];
    __syncthreads();

    // ---- 5. Trilinear form + store ------------------------------------------
    #pragma unroll
    for (int k = 0; k < SPT; k++) {
        float u0[3] = {1.f, C0[k], S0[k]};
        float u1[3] = {1.f, C1[k], S1[k]};
        float z = 0.f;
        #pragma unroll
        for (int p = 0; p < 3; p++) {
            #pragma unroll
            for (int q = 0; q < 3; q++) {
                const float* c3 = &cs[p * 9 + q * 3];
                float w = c3[0];
                w = fmaf(c3[1], C2[k], w);
                w = fmaf(c3[2], S2[k], w);
                z = fmaf(u0[p] * u1[q], w, z);
            }
        }
        int i = gidx + k * T;
        if (i < B) out[i] = z;
    }

    // ---- 6. Replay-safe reset: last block clears the flags ------------------
    __syncthreads();
    if (t == 0) {
        int n = atomicAdd(&g_done, 1);
        if (n == (int)gridDim.x - 1) {
            g_done = 0;
            g_ready = 0;
            __threadfence();
        }
    }
}

extern "C" void kernel_launch(void* const* d_in, const int* in_sizes, int n_in,
                              void* d_out, int out_size) {
    const float* inputs = (const float*)d_in[0];   // (B, 8) float32
    const float* qw     = (const float*)d_in[1];   // (3, 3, 2) float32
    float* out          = (float*)d_out;           // (B, 1) float32

    int B = in_sizes[0] / 8;
    int grid = (B + BLOCK * SPT - 1) / (BLOCK * SPT);   // 512 for B = 2^20

    vqc_one<<<grid, BLOCK>>>((const float4*)inputs, out, qw, B);
}